// round 8
// baseline (speedup 1.0000x reference)
#include <cuda_runtime.h>
#include <cuda_bf16.h>
#include <math.h>

// Problem constants (B, N, M, C, S = 4, 16384, 128, 128, 512)
#define BB    4
#define NPTS  16384
#define MBOX  128
#define CFEAT 128
#define SSAMP 512
#define ROWW  (3 + CFEAT)            // 131 floats per pooled row
#define NBOX  (BB * MBOX)            // 512
#define BOXFLOATS (SSAMP * ROWW)     // 67072 floats per box tile

#define NTHREADS 512
#define NWARPS   (NTHREADS / 32)     // 16
#define SEG      (NPTS / NWARPS)     // 1024 points per warp segment
#define STAGE_PTS 64                 // points staged per warp step
#define OUTER    (SEG / STAGE_PTS)   // 16
#define STAGE_F  (STAGE_PTS * 3)     // 192 floats = 48 float4 per warp

// Emit one pooled row: coords p[0..2] + feats f[0..127] into o[rbase..rbase+130].
// PAD leading scalars; middle = 32 aligned float4; tail = 3-PAD scalars.
// Feature row fetched as ONE coalesced LDG.128 per lane; realigned via shfl;
// tail elements recovered from lane 31's float4 (no extra load).
template<int PAD>
__device__ __forceinline__ void emit_row(float* __restrict__ o, int rbase,
                                         const float* __restrict__ p,
                                         const float* __restrict__ f,
                                         int lane)
{
    const float4 fv = __ldg((const float4*)f + lane);   // f[4*lane .. 4*lane+3]
    float pc = 0.0f;
    if (lane < 3) pc = __ldg(p + lane);                 // coords

    if (PAD > 0 && lane < PAD)
        __stcs(o + rbase + lane, pc);

    float4 v;
    float* vv = (float*)&v;
    #pragma unroll
    for (int k = 0; k < 4; ++k) {
        const int j = k + PAD - 3;                      // compile-time
        float t;
        if (j >= 0) {
            t = (j == 0) ? fv.x : (j == 1) ? fv.y : (j == 2) ? fv.z : fv.w;
        } else {
            const int e4 = j + 4;                       // 1..3, compile-time
            const float src = (e4 == 1) ? fv.y : (e4 == 2) ? fv.z : fv.w;
            t = __shfl_up_sync(0xffffffffu, src, 1);    // lane l-1's element
            const float c = __shfl_sync(0xffffffffu, pc, PAD + k);
            if (lane == 0) t = c;                       // lane-0 hole = coord
        }
        vv[k] = t;
    }
    __stcs((float4*)(o + rbase + PAD + 4 * lane), v);

    // tail: e = PAD+128..130 -> f[PAD+125+t] = lane31's fv component (k = 1+PAD+t)
    if (PAD < 3) {
        float tv = 0.0f;
        if (PAD == 0) {
            const float ty = __shfl_sync(0xffffffffu, fv.y, 31);
            const float tz = __shfl_sync(0xffffffffu, fv.z, 31);
            const float tw = __shfl_sync(0xffffffffu, fv.w, 31);
            tv = (lane == 0) ? ty : (lane == 1) ? tz : tw;
        } else if (PAD == 1) {
            const float tz = __shfl_sync(0xffffffffu, fv.z, 31);
            const float tw = __shfl_sync(0xffffffffu, fv.w, 31);
            tv = (lane == 0) ? tz : tw;
        } else { // PAD == 2
            tv = __shfl_sync(0xffffffffu, fv.w, 31);
        }
        if (lane < 3 - PAD)
            __stcs(o + rbase + PAD + 128 + lane, tv);
    }
}

__global__ __launch_bounds__(NTHREADS, 4)   // 4 CTAs/SM, single wave over grid=512
void roipool3d_kernel(const float* __restrict__ points,   // (B, N, 3)
                      const float* __restrict__ feats,    // (B, N, C)
                      const float* __restrict__ boxes,    // (B, M, 7)
                      float* __restrict__ out,            // (B,M,S,131) then flags (B,M)
                      long long flag_off)
{
    const int bm = blockIdx.x;
    const int b  = bm >> 7;

    // --- Box parameters ---
    const float* box = boxes + (size_t)bm * 7;
    const float cx = box[0];
    const float cy = box[1];
    const float dz = box[5];
    const float cz = box[2] + 0.5f * dz;
    const float dx = box[3];
    const float dy = box[4];
    const float rz = box[6];
    const float cosa = cosf(-rz);
    const float sina = sinf(-rz);
    const float hx = 0.5f * dx;
    const float hy = 0.5f * dy;
    const float hz = 0.5f * dz;

    __shared__ int   s_buf[NWARPS][SSAMP];    // 32 KB: per-warp ordered buffers
    __shared__ float s_stage[NWARPS][STAGE_F];// 12 KB: coalesced point staging
    __shared__ int   s_cnt[NWARPS];
    __shared__ int   s_src[SSAMP];            // 2 KB: wrap-resolved row sources

    const int tid  = threadIdx.x;
    const int wid  = tid >> 5;
    const int lane = tid & 31;
    const unsigned lmask_lt = (1u << lane) - 1u;

    const float* pts = points + (size_t)b * NPTS * 3;

    // --- Phase 1: staged, coalesced point scan + warp-autonomous compaction ---
    {
        const int seg_start = wid * SEG;
        const float4* g4 = (const float4*)(pts + seg_start * 3);  // 16B-aligned
        float4* s4 = (float4*)s_stage[wid];
        int wcnt = 0;

        // prefetch stage 0 (48 float4 per stage: 32 + 16 predicated)
        float4 r0 = __ldg(g4 + lane);
        float4 r1 = make_float4(0.f, 0.f, 0.f, 0.f);
        if (lane < 16) r1 = __ldg(g4 + 32 + lane);

        #pragma unroll 1
        for (int outer = 0; outer < OUTER; ++outer) {
            s4[lane] = r0;
            if (lane < 16) s4[32 + lane] = r1;
            __syncwarp();

            if (outer + 1 < OUTER) {              // prefetch next stage
                const float4* gn = g4 + (outer + 1) * (STAGE_F / 4);
                r0 = __ldg(gn + lane);
                if (lane < 16) r1 = __ldg(gn + 32 + lane);
            }

            #pragma unroll
            for (int sub = 0; sub < 2; ++sub) {
                const int p  = sub * 32 + lane;
                const float px = s_stage[wid][3 * p + 0];  // stride-3: bank-free
                const float py = s_stage[wid][3 * p + 1];
                const float pz = s_stage[wid][3 * p + 2];

                const float sx = px - cx;
                const float sy = py - cy;
                const float lx = sx * cosa - sy * sina;
                const float ly = sx * sina + sy * cosa;

                const bool in =
                    (fabsf(pz - cz) <= hz) &&
                    (fabsf(lx) < hx) &&
                    (fabsf(ly) < hy);

                const unsigned ball = __ballot_sync(0xffffffffu, in);
                const int r = wcnt + __popc(ball & lmask_lt);
                if (in && r < SSAMP)
                    s_buf[wid][r] = seg_start + outer * STAGE_PTS + p;
                wcnt += __popc(ball);
            }
            __syncwarp();
        }
        if (lane == 0) s_cnt[wid] = wcnt;
    }
    __syncthreads();

    // --- Merge + wrap resolution ---
    int total = 0;
    int off   = 0;
    #pragma unroll
    for (int w = 0; w < NWARPS; ++w) {
        const int c = s_cnt[w];
        off   += (w < wid) ? c : 0;
        total += c;
    }
    const int cnt = total;
    {
        const int stored = min(s_cnt[wid], SSAMP);
        for (int k = lane; k < stored; k += 32) {
            const int g = off + k;
            if (g < SSAMP) s_src[g] = s_buf[wid][k];
        }
    }
    __syncthreads();
    if (cnt > 0 && cnt < SSAMP) {
        for (int s = cnt + tid; s < SSAMP; s += NTHREADS)
            s_src[s] = s_src[s % cnt];
        __syncthreads();
    }

    // --- Phase 2: warp-per-row emission (pad = s&3 = wid&3 is warp-constant) ---
    float* o = out + (size_t)bm * BOXFLOATS;

    if (cnt == 0) {
        float4 z = make_float4(0.f, 0.f, 0.f, 0.f);
        float4* o4 = (float4*)o;
        for (int i = tid; i < BOXFLOATS / 4; i += NTHREADS)
            __stcs(o4 + i, z);
    } else {
        const float* fbase = feats + (size_t)b * NPTS * CFEAT;
        switch (wid & 3) {
        case 0:
            #pragma unroll 2
            for (int s = wid; s < SSAMP; s += NWARPS) {
                const int src = s_src[s];
                emit_row<0>(o, s * ROWW, pts + src * 3, fbase + (size_t)src * CFEAT, lane);
            }
            break;
        case 1:
            #pragma unroll 2
            for (int s = wid; s < SSAMP; s += NWARPS) {
                const int src = s_src[s];
                emit_row<1>(o, s * ROWW, pts + src * 3, fbase + (size_t)src * CFEAT, lane);
            }
            break;
        case 2:
            #pragma unroll 2
            for (int s = wid; s < SSAMP; s += NWARPS) {
                const int src = s_src[s];
                emit_row<2>(o, s * ROWW, pts + src * 3, fbase + (size_t)src * CFEAT, lane);
            }
            break;
        default:
            #pragma unroll 2
            for (int s = wid; s < SSAMP; s += NWARPS) {
                const int src = s_src[s];
                emit_row<3>(o, s * ROWW, pts + src * 3, fbase + (size_t)src * CFEAT, lane);
            }
            break;
        }
    }

    // --- Empty flag ---
    if (tid == 0)
        out[flag_off + bm] = (cnt == 0) ? 1.0f : 0.0f;
}

extern "C" void kernel_launch(void* const* d_in, const int* in_sizes, int n_in,
                              void* d_out, int out_size)
{
    const float* points = (const float*)d_in[0];   // (B, N, 3)
    const float* feats  = (const float*)d_in[1];   // (B, N, C)
    const float* boxes  = (const float*)d_in[2];   // (B, M, 7)
    float* out = (float*)d_out;

    const long long flag_off = (long long)out_size - (long long)NBOX;

    roipool3d_kernel<<<NBOX, NTHREADS>>>(points, feats, boxes, out, flag_off);
}

// round 9
// speedup vs baseline: 1.1884x; 1.1884x over previous
#include <cuda_runtime.h>
#include <cuda_bf16.h>
#include <math.h>

// Problem constants (B, N, M, C, S = 4, 16384, 128, 128, 512)
#define BB    4
#define NPTS  16384
#define MBOX  128
#define CFEAT 128
#define SSAMP 512
#define ROWW  (3 + CFEAT)            // 131 floats per pooled row
#define NBOX  (BB * MBOX)            // 512
#define BOXFLOATS (SSAMP * ROWW)     // 67072 floats per box tile

#define NTHREADS 512
#define NWARPS   (NTHREADS / 32)     // 16
#define SEG      (NPTS / NWARPS)     // 1024
#define ITERS    (SEG / 32)          // 32

// ---- Row store: PAD leading scalars, 32 aligned float4, 3-PAD tail scalars.
// Row data in registers: fv = lane's f[4l..4l+3], pc = coord (lanes 0..2).
template<int PAD>
__device__ __forceinline__ void store_row(float* __restrict__ o, int rbase,
                                          float4 fv, float pc, int lane)
{
    if (PAD > 0 && lane < PAD)
        __stcs(o + rbase + lane, pc);

    float4 v;
    float* vv = (float*)&v;
    #pragma unroll
    for (int k = 0; k < 4; ++k) {
        const int j = k + PAD - 3;                      // compile-time
        float t;
        if (j >= 0) {
            t = (j == 0) ? fv.x : (j == 1) ? fv.y : (j == 2) ? fv.z : fv.w;
        } else {
            const int e4 = j + 4;                       // 1..3, compile-time
            const float src = (e4 == 1) ? fv.y : (e4 == 2) ? fv.z : fv.w;
            t = __shfl_up_sync(0xffffffffu, src, 1);    // lane l-1's element
            const float c = __shfl_sync(0xffffffffu, pc, PAD + k);
            if (lane == 0) t = c;                       // lane-0 hole = coord
        }
        vv[k] = t;
    }
    __stcs((float4*)(o + rbase + PAD + 4 * lane), v);

    // tail: e = PAD+128..130 -> f[PAD+125+t] lives in lane 31's fv
    if (PAD < 3) {
        float tv = 0.0f;
        if (PAD == 0) {
            const float ty = __shfl_sync(0xffffffffu, fv.y, 31);
            const float tz = __shfl_sync(0xffffffffu, fv.z, 31);
            const float tw = __shfl_sync(0xffffffffu, fv.w, 31);
            tv = (lane == 0) ? ty : (lane == 1) ? tz : tw;
        } else if (PAD == 1) {
            const float tz = __shfl_sync(0xffffffffu, fv.z, 31);
            const float tw = __shfl_sync(0xffffffffu, fv.w, 31);
            tv = (lane == 0) ? tz : tw;
        } else { // PAD == 2
            tv = __shfl_sync(0xffffffffu, fv.w, 31);
        }
        if (lane < 3 - PAD)
            __stcs(o + rbase + PAD + 128 + lane, tv);
    }
}

__device__ __forceinline__ void store_row_dispatch(float* __restrict__ o, int rbase,
                                                   float4 fv, float pc, int lane)
{
    switch ((4 - (rbase & 3)) & 3) {     // warp-uniform
    case 0: store_row<0>(o, rbase, fv, pc, lane); break;
    case 1: store_row<1>(o, rbase, fv, pc, lane); break;
    case 2: store_row<2>(o, rbase, fv, pc, lane); break;
    default: store_row<3>(o, rbase, fv, pc, lane); break;
    }
}

__global__ __launch_bounds__(NTHREADS, 4)   // 4 CTAs/SM, single wave over grid=512
void roipool3d_kernel(const float* __restrict__ points,   // (B, N, 3)
                      const float* __restrict__ feats,    // (B, N, C)
                      const float* __restrict__ boxes,    // (B, M, 7)
                      float* __restrict__ out,            // (B,M,S,131) then flags (B,M)
                      long long flag_off)
{
    const int bm = blockIdx.x;
    const int b  = bm >> 7;

    // --- Box parameters ---
    const float* box = boxes + (size_t)bm * 7;
    const float cx = box[0];
    const float cy = box[1];
    const float dz = box[5];
    const float cz = box[2] + 0.5f * dz;
    const float dx = box[3];
    const float dy = box[4];
    const float rz = box[6];
    const float cosa = cosf(-rz);
    const float sina = sinf(-rz);
    const float hx = 0.5f * dx;
    const float hy = 0.5f * dy;
    const float hz = 0.5f * dz;

    __shared__ int s_buf[NWARPS][SSAMP];   // 32 KB: per-warp ordered buffers
    __shared__ int s_cnt[NWARPS];
    __shared__ int s_src[SSAMP];           // wrap-resolved source index per row

    const int tid  = threadIdx.x;
    const int wid  = tid >> 5;
    const int lane = tid & 31;
    const unsigned lmask_lt = (1u << lane) - 1u;

    const float* pts = points + (size_t)b * NPTS * 3;

    // --- Phase 1: warp-autonomous ordered compaction (R7: at the L1 wf floor) ---
    {
        const int seg_start = wid * SEG;
        int wcnt = 0;

        #pragma unroll 8
        for (int it = 0; it < ITERS; ++it) {
            const int i = seg_start + it * 32 + lane;
            const float px = pts[i * 3 + 0];
            const float py = pts[i * 3 + 1];
            const float pz = pts[i * 3 + 2];

            const float sx = px - cx;
            const float sy = py - cy;
            const float lx = sx * cosa - sy * sina;
            const float ly = sx * sina + sy * cosa;

            const bool in =
                (fabsf(pz - cz) <= hz) &&
                (fabsf(lx) < hx) &&
                (fabsf(ly) < hy);

            const unsigned ball = __ballot_sync(0xffffffffu, in);
            const int r = wcnt + __popc(ball & lmask_lt);
            if (in && r < SSAMP) s_buf[wid][r] = i;
            wcnt += __popc(ball);
        }
        if (lane == 0) s_cnt[wid] = wcnt;
    }
    __syncthreads();

    // --- Merge + wrap resolution ---
    int total = 0;
    int off   = 0;
    #pragma unroll
    for (int w = 0; w < NWARPS; ++w) {
        const int c = s_cnt[w];
        off   += (w < wid) ? c : 0;
        total += c;
    }
    const int cnt = total;
    {
        const int stored = min(s_cnt[wid], SSAMP);
        for (int k = lane; k < stored; k += 32) {
            const int g = off + k;
            if (g < SSAMP) s_src[g] = s_buf[wid][k];
        }
    }
    __syncthreads();
    if (cnt > 0 && cnt < SSAMP) {
        for (int s = cnt + tid; s < SSAMP; s += NTHREADS)
            s_src[s] = s_src[s % cnt];
        __syncthreads();
    }

    // --- Phase 2 ---
    float* o = out + (size_t)bm * BOXFLOATS;

    if (cnt == 0) {
        float4 z = make_float4(0.f, 0.f, 0.f, 0.f);
        float4* o4 = (float4*)o;
        for (int i = tid; i < BOXFLOATS / 4; i += NTHREADS)
            __stcs(o4 + i, z);
    } else if (cnt >= 16) {
        // Distinct-source mapping: load each row ONCE, store all its duplicates.
        const float* fbase = feats + (size_t)b * NPTS * CFEAT;
        const int jmax = min(cnt, SSAMP);
        for (int j = wid; j < jmax; j += NWARPS) {
            const int src = s_src[j];
            const float* f = fbase + (size_t)src * CFEAT;
            const float4 fv = __ldg((const float4*)f + lane);
            float pc = 0.0f;
            if (lane < 3) pc = __ldg(pts + src * 3 + lane);

            for (int s = j; s < SSAMP; s += cnt)
                store_row_dispatch(o, s * ROWW, fv, pc, lane);
        }
    } else {
        // Few distinct rows: per-row mapping keeps all 16 warps busy;
        // sources are L1-resident. pad = s&3-derived, warp-constant per loop.
        const float* fbase = feats + (size_t)b * NPTS * CFEAT;
        #pragma unroll 2
        for (int s = wid; s < SSAMP; s += NWARPS) {
            const int src = s_src[s];
            const float* f = fbase + (size_t)src * CFEAT;
            const float4 fv = __ldg((const float4*)f + lane);
            float pc = 0.0f;
            if (lane < 3) pc = __ldg(pts + src * 3 + lane);
            store_row_dispatch(o, s * ROWW, fv, pc, lane);
        }
    }

    // --- Empty flag ---
    if (tid == 0)
        out[flag_off + bm] = (cnt == 0) ? 1.0f : 0.0f;
}

extern "C" void kernel_launch(void* const* d_in, const int* in_sizes, int n_in,
                              void* d_out, int out_size)
{
    const float* points = (const float*)d_in[0];   // (B, N, 3)
    const float* feats  = (const float*)d_in[1];   // (B, N, C)
    const float* boxes  = (const float*)d_in[2];   // (B, M, 7)
    float* out = (float*)d_out;

    const long long flag_off = (long long)out_size - (long long)NBOX;

    roipool3d_kernel<<<NBOX, NTHREADS>>>(points, feats, boxes, out, flag_off);
}